// round 9
// baseline (speedup 1.0000x reference)
#include <cuda_runtime.h>
#include <cuda_fp16.h>
#include <cstdint>

// ============================ problem constants ============================
namespace {
constexpr int Bt = 4096;
constexpr int En = 128;
constexpr int IP = 64;
constexpr int HH = 100;
constexpr int NT = 256;          // 8 warps per CTA
constexpr int MR = 128;          // rows per CTA (warp w -> rows w*16..w*16+15)
constexpr int NPAD = 112;        // hidden padded to 14 n8-tiles
constexpr float EPSf  = 1e-5f;
constexpr float SLOPE = 0.01f;

// B smem row stride: 240 bytes (120 halfs). 240/16 = 15 (odd) => the 8 rows
// of an ldmatrix wave land on distinct 16B banks groups: conflict-free.
constexpr int STR = 240;
constexpr int OFF_B1H = 0;                        // [64][STR] fp16 hi of W1
constexpr int OFF_B1L = OFF_B1H + IP * STR;       // 15360: lo of W1
constexpr int OFF_B2H = OFF_B1L + IP * STR;       // 30720: [112][STR] hi of g1*W2
constexpr int OFF_B2L = OFF_B2H + NPAD * STR;     // 57600: lo
constexpr int OFF_BI1 = OFF_B2L + NPAD * STR;     // 84480: float[112] b1
constexpr int OFF_EPI = OFF_BI1 + NPAD * 4;       // 84928: float2[112] (bias2', g2*Wo)
constexpr int OFF_C   = OFF_EPI + NPAD * 8;       // 85824: float[2] C1, C2+bo
constexpr int SMEM_TOTAL = OFF_C + 16;            // 85840
}

// ============================ helpers ============================
__device__ __forceinline__ uint32_t smem_u32(const void* p) {
    uint32_t a;
    asm("{ .reg .u64 t; cvta.to.shared.u64 t, %1; cvt.u32.u64 %0, t; }"
        : "=r"(a) : "l"(p));
    return a;
}
__device__ __forceinline__ uint32_t pack2(float x, float y) {
    __half2 h = __floats2half2_rn(x, y);
    return reinterpret_cast<uint32_t&>(h);
}
// split val into fp16 hi + fp16 lo (val ~= hi + lo)
__device__ __forceinline__ void split2(float x, float y,
                                       uint32_t& hi, uint32_t& lo) {
    const float hx = __half2float(__float2half_rn(x));
    const float hy = __half2float(__float2half_rn(y));
    hi = pack2(hx, hy);
    lo = pack2(x - hx, y - hy);
}
__device__ __forceinline__ void mma16816(float* d, const uint32_t* a,
                                         uint32_t b0, uint32_t b1) {
    asm volatile(
        "mma.sync.aligned.m16n8k16.row.col.f32.f16.f16.f32 "
        "{%0,%1,%2,%3}, {%4,%5,%6,%7}, {%8,%9}, {%0,%1,%2,%3};"
        : "+f"(d[0]), "+f"(d[1]), "+f"(d[2]), "+f"(d[3])
        : "r"(a[0]), "r"(a[1]), "r"(a[2]), "r"(a[3]), "r"(b0), "r"(b1));
}
__device__ __forceinline__ void ldsm_x2_trans(uint32_t& r0, uint32_t& r1,
                                              uint32_t addr) {
    asm volatile("ldmatrix.sync.aligned.m8n8.x2.trans.shared.b16 {%0,%1}, [%2];"
                 : "=r"(r0), "=r"(r1) : "r"(addr));
}

// ============================ kernel ============================
__global__ __launch_bounds__(NT, 1)
void fused_mlp_hmma(const float* __restrict__ x,
                    const float* __restrict__ W1, const float* __restrict__ b1,
                    const float* __restrict__ g1, const float* __restrict__ be1,
                    const float* __restrict__ W2, const float* __restrict__ b2,
                    const float* __restrict__ g2, const float* __restrict__ be2,
                    const float* __restrict__ Wo, const float* __restrict__ bo,
                    float* __restrict__ out)
{
    extern __shared__ char smem[];
    const uint32_t sb = smem_u32(smem);
    const int tid  = threadIdx.x;
    const int e    = blockIdx.y;

    // ---- stage B1 = fp16 hi/lo of W1[e]  ([k=64][n], n-pad 100..111 -> 0) ----
    {
        const float* w1p = W1 + (size_t)e * IP * HH;
        for (int i = tid; i < IP * NPAD; i += NT) {
            const int k = i / NPAD, n = i % NPAD;
            const float w = (n < HH) ? w1p[k * HH + n] : 0.f;
            const __half h = __float2half_rn(w);
            *reinterpret_cast<__half*>(smem + OFF_B1H + k * STR + n * 2) = h;
            *reinterpret_cast<__half*>(smem + OFF_B1L + k * STR + n * 2) =
                __float2half_rn(w - __half2float(h));
        }
    }
    // ---- stage B2 = fp16 hi/lo of g1*W2[e]  ([k=112][n], pads -> 0) ----
    {
        const float* w2p = W2 + (size_t)e * HH * HH;
        const float* g1p = g1 + e * HH;
        for (int i = tid; i < NPAD * NPAD; i += NT) {
            const int k = i / NPAD, n = i % NPAD;
            const float w = (k < HH && n < HH) ? w2p[k * HH + n] * g1p[k] : 0.f;
            const __half h = __float2half_rn(w);
            *reinterpret_cast<__half*>(smem + OFF_B2H + k * STR + n * 2) = h;
            *reinterpret_cast<__half*>(smem + OFF_B2L + k * STR + n * 2) =
                __float2half_rn(w - __half2float(h));
        }
    }
    // ---- per-col constants ----
    if (tid < NPAD) {
        const int n = tid;
        float bias1 = 0.f, bias2 = 0.f, gw = 0.f;
        if (n < HH) {
            bias1 = b1[e * HH + n];
            const float* w2p  = W2  + (size_t)e * HH * HH + n;
            const float* be1p = be1 + e * HH;
            float acc = b2[e * HH + n];
            #pragma unroll 4
            for (int k = 0; k < HH; k++)
                acc = fmaf(be1p[k], w2p[(size_t)k * HH], acc);
            bias2 = acc;
            gw = g2[e * HH + n] * Wo[e * HH + n];
        }
        reinterpret_cast<float*>(smem + OFF_BI1)[n] = bias1;
        reinterpret_cast<float2*>(smem + OFF_EPI)[n] = make_float2(bias2, gw);
    }
    if (tid == NT - 1) {
        float c1 = 0.f, c2 = 0.f;
        const float* g2p  = g2  + e * HH;
        const float* be2p = be2 + e * HH;
        const float* wop  = Wo  + e * HH;
        #pragma unroll 4
        for (int j = 0; j < HH; j++) {
            c1 = fmaf(g2p[j],  wop[j], c1);
            c2 = fmaf(be2p[j], wop[j], c2);
        }
        reinterpret_cast<float*>(smem + OFF_C)[0] = c1;
        reinterpret_cast<float*>(smem + OFF_C)[1] = c2 + bo[e];
    }
    __syncthreads();

    // ---- warp/thread geometry ----
    const int lane = tid & 31;
    const int warp = tid >> 5;
    const int r0 = blockIdx.x * MR + warp * 16 + (lane >> 2);  // row (lane/4)
    const int qk = (lane & 3) * 2;                             // k/n pair base
    const uint32_t lrow = (uint32_t)(lane & 15);               // ldmatrix row idx

    // =================== GEMM1: D1 = x @ W1 (3-term fp16 split) ==============
    float d[14][4];
    #pragma unroll
    for (int t = 0; t < 14; t++)
        d[t][0] = d[t][1] = d[t][2] = d[t][3] = 0.f;

    const float* xr0 = x + ((size_t)r0 * En + e) * IP;
    const float* xr1 = xr0 + (size_t)8 * En * IP;  // row + 8

    #pragma unroll
    for (int kc = 0; kc < 4; kc++) {
        const int k0 = kc * 16 + qk;
        // A fragments: a0=(r,k) a1=(r+8,k) a2=(r,k+8) a3=(r+8,k+8)
        const float2 v0 = *reinterpret_cast<const float2*>(xr0 + k0);
        const float2 v1 = *reinterpret_cast<const float2*>(xr1 + k0);
        const float2 v2 = *reinterpret_cast<const float2*>(xr0 + k0 + 8);
        const float2 v3 = *reinterpret_cast<const float2*>(xr1 + k0 + 8);
        uint32_t ah[4], al[4];
        split2(v0.x, v0.y, ah[0], al[0]);
        split2(v1.x, v1.y, ah[1], al[1]);
        split2(v2.x, v2.y, ah[2], al[2]);
        split2(v3.x, v3.y, ah[3], al[3]);

        const uint32_t rowb = (uint32_t)(kc * 16) + lrow;
        #pragma unroll
        for (int nt = 0; nt < 14; nt++) {
            uint32_t bh0, bh1, bl0, bl1;
            ldsm_x2_trans(bh0, bh1, sb + OFF_B1H + rowb * STR + nt * 16);
            ldsm_x2_trans(bl0, bl1, sb + OFF_B1L + rowb * STR + nt * 16);
            mma16816(d[nt], ah, bh0, bh1);
            mma16816(d[nt], ah, bl0, bl1);
            mma16816(d[nt], al, bh0, bh1);
        }
    }

    // =================== epilogue 1: bias + leaky + LN1 ======================
    const float* bi1 = reinterpret_cast<const float*>(smem + OFF_BI1);
    float s0 = 0.f, q0 = 0.f, s1 = 0.f, q1 = 0.f;
    #pragma unroll
    for (int t = 0; t < 14; t++) {
        #pragma unroll
        for (int j = 0; j < 2; j++) {
            const float bn = bi1[t * 8 + qk + j];
            float a = d[t][j] + bn;     a = fmaxf(a, SLOPE * a);
            d[t][j] = a;  s0 += a;  q0 = fmaf(a, a, q0);
            float c = d[t][2 + j] + bn; c = fmaxf(c, SLOPE * c);
            d[t][2 + j] = c;  s1 += c;  q1 = fmaf(c, c, q1);
        }
    }
    s0 += __shfl_xor_sync(0xffffffffu, s0, 1); s0 += __shfl_xor_sync(0xffffffffu, s0, 2);
    q0 += __shfl_xor_sync(0xffffffffu, q0, 1); q0 += __shfl_xor_sync(0xffffffffu, q0, 2);
    s1 += __shfl_xor_sync(0xffffffffu, s1, 1); s1 += __shfl_xor_sync(0xffffffffu, s1, 2);
    q1 += __shfl_xor_sync(0xffffffffu, q1, 1); q1 += __shfl_xor_sync(0xffffffffu, q1, 2);
    const float inv = 1.f / (float)HH;
    const float m0 = s0 * inv, rs0 = rsqrtf(fmaf(-m0, m0, q0 * inv) + EPSf);
    const float m1 = s1 * inv, rs1 = rsqrtf(fmaf(-m1, m1, q1 * inv) + EPSf);

    // repack normalized h into A2 fragments (register-only; D tile pair 2c,2c+1
    // forms the m16k16 A fragment for K-chunk c)
    uint32_t a2h[7][4], a2l[7][4];
    #pragma unroll
    for (int c = 0; c < 7; c++) {
        const int t0 = 2 * c, t1 = 2 * c + 1;
        split2((d[t0][0] - m0) * rs0, (d[t0][1] - m0) * rs0, a2h[c][0], a2l[c][0]);
        split2((d[t0][2] - m1) * rs1, (d[t0][3] - m1) * rs1, a2h[c][1], a2l[c][1]);
        split2((d[t1][0] - m0) * rs0, (d[t1][1] - m0) * rs0, a2h[c][2], a2l[c][2]);
        split2((d[t1][2] - m1) * rs1, (d[t1][3] - m1) * rs1, a2h[c][3], a2l[c][3]);
    }

    // =================== GEMM2: D2 = h @ (g1*W2) =============================
    #pragma unroll
    for (int t = 0; t < 14; t++)
        d[t][0] = d[t][1] = d[t][2] = d[t][3] = 0.f;

    #pragma unroll
    for (int c = 0; c < 7; c++) {
        const uint32_t rowb = (uint32_t)(c * 16) + lrow;
        #pragma unroll
        for (int nt = 0; nt < 14; nt++) {
            uint32_t bh0, bh1, bl0, bl1;
            ldsm_x2_trans(bh0, bh1, sb + OFF_B2H + rowb * STR + nt * 16);
            ldsm_x2_trans(bl0, bl1, sb + OFF_B2L + rowb * STR + nt * 16);
            mma16816(d[nt], a2h[c], bh0, bh1);
            mma16816(d[nt], a2h[c], bl0, bl1);
            mma16816(d[nt], a2l[c], bh0, bh1);
        }
    }

    // =================== epilogue 2: leaky + LN2/head folded =================
    const float2* epi = reinterpret_cast<const float2*>(smem + OFF_EPI);
    float t0s = 0.f, t0q = 0.f, t0w = 0.f, t1s = 0.f, t1q = 0.f, t1w = 0.f;
    #pragma unroll
    for (int t = 0; t < 14; t++) {
        #pragma unroll
        for (int j = 0; j < 2; j++) {
            const float2 en = epi[t * 8 + qk + j];
            float a = d[t][j] + en.x;     a = fmaxf(a, SLOPE * a);
            t0s += a;  t0q = fmaf(a, a, t0q);  t0w = fmaf(a, en.y, t0w);
            float c = d[t][2 + j] + en.x; c = fmaxf(c, SLOPE * c);
            t1s += c;  t1q = fmaf(c, c, t1q);  t1w = fmaf(c, en.y, t1w);
        }
    }
    t0s += __shfl_xor_sync(0xffffffffu, t0s, 1); t0s += __shfl_xor_sync(0xffffffffu, t0s, 2);
    t0q += __shfl_xor_sync(0xffffffffu, t0q, 1); t0q += __shfl_xor_sync(0xffffffffu, t0q, 2);
    t0w += __shfl_xor_sync(0xffffffffu, t0w, 1); t0w += __shfl_xor_sync(0xffffffffu, t0w, 2);
    t1s += __shfl_xor_sync(0xffffffffu, t1s, 1); t1s += __shfl_xor_sync(0xffffffffu, t1s, 2);
    t1q += __shfl_xor_sync(0xffffffffu, t1q, 1); t1q += __shfl_xor_sync(0xffffffffu, t1q, 2);
    t1w += __shfl_xor_sync(0xffffffffu, t1w, 1); t1w += __shfl_xor_sync(0xffffffffu, t1w, 2);

    if ((lane & 3) == 0) {
        const float C1 = reinterpret_cast<const float*>(smem + OFF_C)[0];
        const float C2 = reinterpret_cast<const float*>(smem + OFF_C)[1];
        {
            const float mm = t0s * inv;
            const float rr = rsqrtf(fmaf(-mm, mm, t0q * inv) + EPSf);
            out[(size_t)e * Bt + r0] = fmaf(rr, fmaf(-mm, C1, t0w), C2);
        }
        {
            const float mm = t1s * inv;
            const float rr = rsqrtf(fmaf(-mm, mm, t1q * inv) + EPSf);
            out[(size_t)e * Bt + r0 + 8] = fmaf(rr, fmaf(-mm, C1, t1w), C2);
        }
    }
}

// ============================ launch ============================
extern "C" void kernel_launch(void* const* d_in, const int* in_sizes, int n_in,
                              void* d_out, int out_size)
{
    const float* x   = (const float*)d_in[0];
    const float* W1  = (const float*)d_in[1];
    const float* b1  = (const float*)d_in[2];
    const float* g1  = (const float*)d_in[3];
    const float* be1 = (const float*)d_in[4];
    const float* W2  = (const float*)d_in[5];
    const float* b2  = (const float*)d_in[6];
    const float* g2  = (const float*)d_in[7];
    const float* be2 = (const float*)d_in[8];
    const float* Wo  = (const float*)d_in[9];
    const float* bo  = (const float*)d_in[10];
    float* out = (float*)d_out;

    cudaFuncSetAttribute(fused_mlp_hmma,
                         cudaFuncAttributeMaxDynamicSharedMemorySize, SMEM_TOTAL);
    dim3 grid(Bt / MR, En);   // (32, 128)
    fused_mlp_hmma<<<grid, NT, SMEM_TOTAL>>>(x, W1, b1, g1, be1,
                                             W2, b2, g2, be2, Wo, bo, out);
}